// round 8
// baseline (speedup 1.0000x reference)
#include <cuda_runtime.h>
#include <cuda_fp16.h>
#include <stdint.h>
#include <math.h>

#define N_NODES 50000
#define N_EDGES 800000
#define D 128
#define H 256

// ---------------- device scratch ----------------
__device__ __align__(16) float  g_n  [(size_t)N_NODES * D];
__device__ __align__(16) __half g_nh [(size_t)N_NODES * D];
__device__ __align__(16) __half g_eh [(size_t)N_EDGES * D];
__device__ __align__(16) __half g_Psh[(size_t)N_NODES * H];
__device__ __align__(16) __half g_Prh[(size_t)N_NODES * H];
__device__ __align__(16) float  g_agg[(size_t)N_NODES * D];
// pre-transposed fp16 weights ([N][K] K-major)
__device__ __align__(16) __half g_wnt[128 * 128];
__device__ __align__(16) __half g_wet[128 * 128];
__device__ __align__(16) __half g_w1t[9 * 256 * 128];
__device__ __align__(16) __half g_w2t[3 * 128 * 256];
__device__ __align__(16) __half g_wut[3 * 128 * 256];

__device__ __forceinline__ uint32_t s2u(const void* p) {
    uint32_t a;
    asm("{ .reg .u64 t; cvta.to.shared.u64 t, %1; cvt.u32.u64 %0, t; }" : "=r"(a) : "l"(p));
    return a;
}
__device__ __forceinline__ void ldsm4(uint32_t* r, uint32_t a) {
    asm volatile("ldmatrix.sync.aligned.m8n8.x4.shared.b16 {%0,%1,%2,%3}, [%4];"
        : "=r"(r[0]), "=r"(r[1]), "=r"(r[2]), "=r"(r[3]) : "r"(a));
}
__device__ __forceinline__ void mma16816(float* c, const uint32_t* a, uint32_t b0, uint32_t b1) {
    asm volatile("mma.sync.aligned.m16n8k16.row.col.f32.f16.f16.f32 "
        "{%0,%1,%2,%3},{%4,%5,%6,%7},{%8,%9},{%0,%1,%2,%3};"
        : "+f"(c[0]), "+f"(c[1]), "+f"(c[2]), "+f"(c[3])
        : "r"(a[0]), "r"(a[1]), "r"(a[2]), "r"(a[3]), "r"(b0), "r"(b1));
}
__device__ __forceinline__ void bar_sync(int id, int cnt) {
    asm volatile("bar.sync %0, %1;" :: "r"(id), "r"(cnt) : "memory");
}
__device__ __forceinline__ void bar_arrive(int id, int cnt) {
    asm volatile("bar.arrive %0, %1;" :: "r"(id), "r"(cnt) : "memory");
}
__device__ __forceinline__ float gelu_tanh(float x) {
    const float c = 0.7978845608028654f;
    float t = tanhf(c * (x + 0.044715f * x * x * x));
    return 0.5f * x * (1.0f + t);
}

// ------------- padded-row GEMM core (SA = K*2+16) — used by non-edge kernels -------------
template<int K, int NTW>
__device__ __forceinline__ void mma_loop(uint32_t abase, uint32_t bbase,
                                         float (&acc)[2][NTW][4], int wm, int wn, int lane)
{
    const int SA = K * 2 + 16;
    int mat  = lane >> 3;
    int arow = (lane & 7) + ((mat & 1) << 3);
    int akb  = (mat >> 1) << 4;
    int brow = (lane & 7) + ((mat >> 1) << 3);
    int bkb  = (mat & 1) << 4;
    uint32_t a0 = abase + (wm * 32 + arow) * SA + akb;
    uint32_t b0 = bbase + (wn * (8 * NTW) + brow) * SA + bkb;
#pragma unroll
    for (int kt = 0; kt < K / 16; kt++) {
        uint32_t A[2][4], B[NTW / 2][4];
        ldsm4(A[0], a0 + kt * 32);
        ldsm4(A[1], a0 + 16 * SA + kt * 32);
#pragma unroll
        for (int j = 0; j < NTW / 2; j++)
            ldsm4(B[j], b0 + j * 16 * SA + kt * 32);
#pragma unroll
        for (int i = 0; i < 2; i++)
#pragma unroll
            for (int j = 0; j < NTW / 2; j++) {
                mma16816(acc[i][2 * j],     A[i], B[j][0], B[j][1]);
                mma16816(acc[i][2 * j + 1], A[i], B[j][2], B[j][3]);
            }
    }
}

// ------------- swizzled GEMM core (row stride SA/SB, offset XOR (row&7)<<4) -------------
template<int K, int NTW, int SA, int SB>
__device__ __forceinline__ void mma_loop_sw(uint32_t abase, uint32_t bbase,
                                            float (&acc)[2][NTW][4], int wm, int wn, int lane)
{
    int mat  = lane >> 3;
    int arow = (lane & 7) + ((mat & 1) << 3);
    int akb  = (mat >> 1) << 4;
    int brow = (lane & 7) + ((mat >> 1) << 3);
    int bkb  = (mat & 1) << 4;
    uint32_t ar0 = wm * 32 + arow, ar1 = ar0 + 16;
    uint32_t sw_a = (ar0 & 7) << 4;
#pragma unroll
    for (int kt = 0; kt < K / 16; kt++) {
        uint32_t A[2][4], B[NTW / 2][4];
        uint32_t ak = (uint32_t)(akb + kt * 32);
        ldsm4(A[0], abase + ar0 * SA + (ak ^ sw_a));
        ldsm4(A[1], abase + ar1 * SA + (ak ^ sw_a));
#pragma unroll
        for (int j = 0; j < NTW / 2; j++) {
            uint32_t br = wn * (8 * NTW) + brow + j * 16;
            uint32_t bk = (uint32_t)(bkb + kt * 32);
            ldsm4(B[j], bbase + br * SB + (bk ^ ((br & 7) << 4)));
        }
#pragma unroll
        for (int i = 0; i < 2; i++)
#pragma unroll
            for (int j = 0; j < NTW / 2; j++) {
                mma16816(acc[i][2 * j],     A[i], B[j][0], B[j][1]);
                mma16816(acc[i][2 * j + 1], A[i], B[j][2], B[j][3]);
            }
    }
}

template<int K>
__device__ __forceinline__ void stage_rows(char* dst, const __half* src, size_t row0, int M)
{
    const int SA = K * 2 + 16, CH = K / 8;
    for (int i = threadIdx.x; i < 128 * CH; i += 512) {
        int r = i / CH, c = i % CH;
        uint4 v = make_uint4(0, 0, 0, 0);
        if (row0 + r < (size_t)M) v = *(const uint4*)(src + (row0 + r) * K + c * 8);
        *(uint4*)(dst + r * SA + c * 16) = v;
    }
}
template<int K>
__device__ __forceinline__ void stage_w(char* dst, const __half* src, int rows)
{
    const int SA = K * 2 + 16, CH = K / 8;
    for (int i = threadIdx.x; i < rows * CH; i += 512)
        *(uint4*)(dst + (i / CH) * SA + (i % CH) * 16) = ((const uint4*)src)[i];
}

// =====================================================================================
// transpose_all: one launch for all 17 weight transposes (f32 [K][N] -> f16 [N][K])
// =====================================================================================
__global__ void transpose_all(const float* __restrict__ w_node, const float* __restrict__ w_edge,
                              const float* __restrict__ msg_w1, const float* __restrict__ msg_w2,
                              const float* __restrict__ upd_w,
                              __half* __restrict__ wnt, __half* __restrict__ wet,
                              __half* __restrict__ w1t, __half* __restrict__ w2t,
                              __half* __restrict__ wut)
{
    int z = blockIdx.z;
    const float* src; __half* dst; int K, N;
    if (z == 0)      { src = w_node; dst = wnt; K = 128; N = 128; }
    else if (z == 1) { src = w_edge; dst = wet; K = 128; N = 128; }
    else if (z < 11) {
        int j = z - 2, l = j / 3, p = j % 3;
        src = msg_w1 + (size_t)l * 384 * 256 + (size_t)p * 128 * 256;
        dst = w1t + (size_t)j * 32768; K = 128; N = 256;
    } else if (z < 14) {
        int l = z - 11;
        src = msg_w2 + (size_t)l * 256 * 128; dst = w2t + (size_t)l * 32768; K = 256; N = 128;
    } else {
        int l = z - 14;
        src = upd_w + (size_t)l * 256 * 128; dst = wut + (size_t)l * 32768; K = 256; N = 128;
    }
    int k0 = blockIdx.x * 32, n0 = blockIdx.y * 32;
    if (k0 >= K || n0 >= N) return;
    __shared__ float t[32][33];
    int tx = threadIdx.x & 31, ty = threadIdx.x >> 5;
    for (int i = ty; i < 32; i += 8) {
        int k = k0 + i, n = n0 + tx;
        t[i][tx] = (k < K && n < N) ? src[(size_t)k * N + n] : 0.f;
    }
    __syncthreads();
    for (int i = ty; i < 32; i += 8) {
        int n = n0 + i, k = k0 + tx;
        if (n < N && k < K) dst[(size_t)n * K + k] = __float2half(t[tx][i]);
    }
}

// =====================================================================================
// embed: out = LN(gelu(x@W + b)). K=128, N=128.
// =====================================================================================
__global__ __launch_bounds__(512, 1)
void embed_f16(const float* __restrict__ x, const __half* __restrict__ Wt,
               const float* __restrict__ bias,
               const float* __restrict__ lns, const float* __restrict__ lno,
               float* __restrict__ outf, __half* __restrict__ outh, int M)
{
    extern __shared__ char sm[];
    char* Asm = sm;
    char* Bsm = sm + 34816;
    const int tid = threadIdx.x, w = tid >> 5, lane = tid & 31;
    const size_t row0 = (size_t)blockIdx.x * 128;

    for (int i = tid; i < 128 * 16; i += 512) {
        int r = i >> 4, c = i & 15;
        uint32_t o[4] = {0, 0, 0, 0};
        if (row0 + r < (size_t)M) {
            const float* src = x + (row0 + r) * 128 + c * 8;
            float4 a = ((const float4*)src)[0], b = ((const float4*)src)[1];
            __half2 h0 = __floats2half2_rn(a.x, a.y), h1 = __floats2half2_rn(a.z, a.w);
            __half2 h2 = __floats2half2_rn(b.x, b.y), h3 = __floats2half2_rn(b.z, b.w);
            o[0] = *(uint32_t*)&h0; o[1] = *(uint32_t*)&h1; o[2] = *(uint32_t*)&h2; o[3] = *(uint32_t*)&h3;
        }
        *(uint4*)(Asm + r * 272 + c * 16) = *(uint4*)o;
    }
    stage_w<128>(Bsm, Wt, 128);
    __syncthreads();

    float acc[2][4][4] = {};
    mma_loop<128, 4>(s2u(Asm), s2u(Bsm), acc, w >> 2, w & 3, lane);
    __syncthreads();

    float* Csm = (float*)sm;   // 128 x 132
    const int gid = lane >> 2, tig = lane & 3;
    const int rb = (w >> 2) * 32 + gid, cb = (w & 3) * 32 + tig * 2;
#pragma unroll
    for (int i = 0; i < 2; i++)
#pragma unroll
        for (int nt = 0; nt < 4; nt++) {
            int col = cb + nt * 8;
            int r = rb + i * 16;
            Csm[r * 132 + col]           = gelu_tanh(acc[i][nt][0] + bias[col]);
            Csm[r * 132 + col + 1]       = gelu_tanh(acc[i][nt][1] + bias[col + 1]);
            Csm[(r + 8) * 132 + col]     = gelu_tanh(acc[i][nt][2] + bias[col]);
            Csm[(r + 8) * 132 + col + 1] = gelu_tanh(acc[i][nt][3] + bias[col + 1]);
        }
    __syncthreads();

    int r = tid >> 2, s = tid & 3;
    float4 v[8];
    float sum = 0.f;
#pragma unroll
    for (int k = 0; k < 8; k++) {
        v[k] = *(float4*)&Csm[r * 132 + s * 4 + k * 16];
        sum += v[k].x + v[k].y + v[k].z + v[k].w;
    }
    sum += __shfl_xor_sync(0xffffffffu, sum, 1);
    sum += __shfl_xor_sync(0xffffffffu, sum, 2);
    float mean = sum * (1.0f / 128.0f);
    float q = 0.f;
#pragma unroll
    for (int k = 0; k < 8; k++) {
        float dx = v[k].x - mean, dy = v[k].y - mean, dz = v[k].z - mean, dw = v[k].w - mean;
        q += dx * dx + dy * dy + dz * dz + dw * dw;
    }
    q += __shfl_xor_sync(0xffffffffu, q, 1);
    q += __shfl_xor_sync(0xffffffffu, q, 2);
    float rstd = rsqrtf(q * (1.0f / 128.0f) + 1e-5f);

    size_t row = row0 + r;
    if (row < (size_t)M) {
#pragma unroll
        for (int k = 0; k < 8; k++) {
            int col = s * 4 + k * 16;
            float4 sc = *(const float4*)(lns + col), of = *(const float4*)(lno + col);
            float4 o;
            o.x = (v[k].x - mean) * rstd * sc.x + of.x;
            o.y = (v[k].y - mean) * rstd * sc.y + of.y;
            o.z = (v[k].z - mean) * rstd * sc.z + of.z;
            o.w = (v[k].w - mean) * rstd * sc.w + of.w;
            if (outf) *(float4*)(outf + row * 128 + col) = o;
            if (outh) {
                __half2 h0 = __floats2half2_rn(o.x, o.y), h1 = __floats2half2_rn(o.z, o.w);
                ((uint32_t*)(outh + row * 128 + col))[0] = *(uint32_t*)&h0;
                ((uint32_t*)(outh + row * 128 + col))[1] = *(uint32_t*)&h1;
            }
        }
    }
}

// =====================================================================================
// gemm1x2: C1 = A@B1t^T, C2 = A@B2t^T
// =====================================================================================
__global__ __launch_bounds__(512, 1)
void gemm1x2_f16(const __half* __restrict__ A,
                 const __half* __restrict__ B1t, const __half* __restrict__ B2t,
                 __half* __restrict__ C1, __half* __restrict__ C2, int M)
{
    extern __shared__ char sm[];
    char* Asm  = sm;
    char* Bsm1 = sm + 34816;
    char* Bsm2 = sm + 34816 + 69632;
    const int tid = threadIdx.x, w = tid >> 5, lane = tid & 31;
    const size_t row0 = (size_t)blockIdx.x * 128;

    stage_rows<128>(Asm, A, row0, M);
    stage_w<128>(Bsm1, B1t, 256);
    stage_w<128>(Bsm2, B2t, 256);
    __syncthreads();

    const int gid = lane >> 2, tig = lane & 3;
    const int rb = (w >> 2) * 32 + gid, cb = (w & 3) * 64 + tig * 2;

#pragma unroll
    for (int pass = 0; pass < 2; pass++) {
        float acc[2][8][4] = {};
        mma_loop<128, 8>(s2u(Asm), s2u(pass ? Bsm2 : Bsm1), acc, w >> 2, w & 3, lane);
        __half* C = pass ? C2 : C1;
#pragma unroll
        for (int i = 0; i < 2; i++) {
            size_t r = row0 + rb + i * 16;
#pragma unroll
            for (int nt = 0; nt < 8; nt++) {
                int col = cb + nt * 8;
                __half2 h01 = __floats2half2_rn(acc[i][nt][0], acc[i][nt][1]);
                __half2 h23 = __floats2half2_rn(acc[i][nt][2], acc[i][nt][3]);
                if (r < (size_t)M)     *(__half2*)(C + r * 256 + col) = h01;
                if (r + 8 < (size_t)M) *(__half2*)(C + (r + 8) * 256 + col) = h23;
            }
        }
    }
}

// =====================================================================================
// edge_ws: warp-specialized persistent edge kernel, 64-edge tiles.
//   IO warps (8): prefetch idx, A_e, and G = Ps[s]+Pr[r]+b1 for block t+1
//   Compute warps (8): mma1 (Pe) -> m1 = relu(Pe+G) in place -> mma2 -> direct float2 RED
// smem layout (bytes):
//   B1 0..65536 | B2 ..131072 | AE 2x16384 ..163840 | Gb 2x32768 ..229376
//   IDX 2x512 ..230400 | b1h 512 ..230912
// =====================================================================================
__global__ __launch_bounds__(512, 1)
void edge_ws_f16(const __half* __restrict__ eh,
                 const __half* __restrict__ Ps, const __half* __restrict__ Pr,
                 const __half* __restrict__ W1ct, const float* __restrict__ b1,
                 const __half* __restrict__ W2t,  const float* __restrict__ b2,
                 const int* __restrict__ snd, const int* __restrict__ rcv,
                 float* __restrict__ agg, int E)
{
    extern __shared__ char sm[];
    char* B1 = sm;                                   // 65536
    char* B2 = sm + 65536;                           // 65536
    char* AE = sm + 131072;                          // 2 x 16384
    char* Gb = sm + 163840;                          // 2 x 32768
    int*  IDX = (int*)(sm + 229376);                 // 2 x (64 snd + 64 rcv) = 1024 B
    __half2* b1h = (__half2*)(sm + 230400);          // 128 half2 = 512 B
    const int tid = threadIdx.x;
    const int w = tid >> 5, lane = tid & 31;

    // stage weights + b1 (all threads)
    for (int i = tid; i < 256 * 16; i += 512) {      // B1: 256 rows x 16 chunks, swizzled
        int r = i >> 4, c = i & 15;
        *(uint4*)(B1 + r * 256 + (((uint32_t)c * 16) ^ ((r & 7) << 4))) =
            *(const uint4*)(W1ct + (size_t)r * 128 + c * 8);
    }
    for (int i = tid; i < 128 * 32; i += 512) {      // B2: 128 rows x 32 chunks
        int r = i >> 5, c = i & 31;
        *(uint4*)(B2 + r * 512 + (((uint32_t)c * 16) ^ ((r & 7) << 4))) =
            *(const uint4*)(W2t + (size_t)r * 256 + c * 8);
    }
    if (tid < 128) b1h[tid] = __floats2half2_rn(b1[2 * tid], b1[2 * tid + 1]);
    __syncthreads();

    const int nblk = (E + 63) >> 6;
    const int bx = blockIdx.x, gsz = gridDim.x;
    const int T = (nblk > bx) ? ((nblk - bx + gsz - 1) / gsz) : 0;
    if (T <= 0) return;

    if (w >= 8) {
        // -------- IO group (256 threads) --------
        const int t2 = tid - 256;
        auto prepare = [&](int u) {
            if (u >= T) return;
            int blk = bx + u * gsz;
            int e0 = blk << 6;
            int slot = u & 1;
            int* sI = IDX + slot * 128;
            int* rI = sI + 64;
            if (t2 < 64) {
                int eg = e0 + t2;
                sI[t2] = (eg < E) ? snd[eg] : -1;
                rI[t2] = (eg < E) ? rcv[eg] : -1;
            }
            bar_sync(4, 256);   // io-internal: idx visible
            char* ae = AE + slot * 16384;
            for (int i = t2; i < 64 * 16; i += 256) {
                int r = i >> 4, c = i & 15;
                uint4 v = make_uint4(0, 0, 0, 0);
                int eg = e0 + r;
                if (eg < E) v = *(const uint4*)(eh + (size_t)eg * 128 + c * 8);
                *(uint4*)(ae + r * 256 + (((uint32_t)c * 16) ^ ((r & 7) << 4))) = v;
            }
            char* g = Gb + slot * 32768;
            for (int i = t2; i < 64 * 32; i += 256) {
                int r = i >> 5, c = i & 31;
                int sv = sI[r], rv = rI[r];
                uint32_t o[4] = {0, 0, 0, 0};
                if (sv >= 0) {
                    uint4 pa = *(const uint4*)(Ps + (size_t)sv * 256 + c * 8);
                    uint4 pb = *(const uint4*)(Pr + (size_t)rv * 256 + c * 8);
#pragma unroll
                    for (int q = 0; q < 4; q++) {
                        __half2 hv = __hadd2(__hadd2(((__half2*)&pa)[q], ((__half2*)&pb)[q]),
                                             b1h[c * 4 + q]);
                        o[q] = *(uint32_t*)&hv;
                    }
                }
                *(uint4*)(g + r * 512 + (((uint32_t)c * 16) ^ ((r & 7) << 4))) = *(uint4*)o;
            }
        };
        prepare(0);
        bar_arrive(1, 512);
        prepare(1);
        bar_arrive(5, 512);
        for (int u = 2; u < T; u++) {
            bar_sync((u & 1) ? 6 : 2, 512);
            prepare(u);
            bar_arrive((u & 1) ? 5 : 1, 512);
        }
    } else {
        // -------- compute group (256 threads) --------
        const int wm = (w >> 2) & 1, wn = w & 3;
        const int gid = lane >> 2, tig = lane & 3;
        for (int t = 0; t < T; t++) {
            int slot = t & 1;
            char* ae = AE + slot * 16384;
            char* g  = Gb + slot * 32768;
            int* rI = IDX + slot * 128 + 64;

            bar_sync((t & 1) ? 5 : 1, 512);

            // snapshot receiver ids into regs BEFORE releasing buffers (race fix)
            int rv[4];
#pragma unroll
            for (int i = 0; i < 4; i++)
                rv[i] = rI[wm * 32 + gid + i * 8];

            // mma1: Pe = A_e @ W1c^T  (64x256, K=128)
            float acc[2][8][4] = {};
            mma_loop_sw<128, 8, 256, 256>(s2u(ae), s2u(B1), acc, wm, wn, lane);

            // epilogue: m1 = relu(Pe + G) in place (each element exclusively owned)
#pragma unroll
            for (int i = 0; i < 2; i++) {
#pragma unroll
                for (int nt = 0; nt < 8; nt++) {
                    int col = wn * 64 + nt * 8 + tig * 2;
                    uint32_t cb2 = (uint32_t)(col * 2);
#pragma unroll
                    for (int hh = 0; hh < 2; hh++) {
                        int r = wm * 32 + gid + i * 16 + hh * 8;
                        uint32_t byte = r * 512 + (cb2 ^ ((r & 7) << 4));
                        __half2* p = (__half2*)(g + byte);
                        float2 gf = __half22float2(*p);
                        float x = fmaxf(gf.x + acc[i][nt][2 * hh],     0.f);
                        float y = fmaxf(gf.y + acc[i][nt][2 * hh + 1], 0.f);
                        *p = __floats2half2_rn(x, y);
                    }
                }
            }
            bar_sync(3, 256);   // all m1 written before mma2 reads

            // mma2: out = m1 @ W2^T  (64x128, K=256)
            float acc2[2][4][4] = {};
            mma_loop_sw<256, 4, 512, 512>(s2u(g), s2u(B2), acc2, wm, wn, lane);

            bar_arrive((t & 1) ? 6 : 2, 512);   // buffers free for io

            // direct float2 RED scatter with bias+relu (indices in regs)
#pragma unroll
            for (int i = 0; i < 2; i++) {
                int rv0 = rv[i * 2], rv1 = rv[i * 2 + 1];
#pragma unroll
                for (int nt = 0; nt < 4; nt++) {
                    int col = wn * 32 + nt * 8 + tig * 2;
                    float2 bb = *(const float2*)(b2 + col);
                    if (rv0 >= 0) {
                        float2 v0 = make_float2(fmaxf(acc2[i][nt][0] + bb.x, 0.f),
                                                fmaxf(acc2[i][nt][1] + bb.y, 0.f));
                        atomicAdd((float2*)(agg + (size_t)rv0 * 128 + col), v0);
                    }
                    if (rv1 >= 0) {
                        float2 v1 = make_float2(fmaxf(acc2[i][nt][2] + bb.x, 0.f),
                                                fmaxf(acc2[i][nt][3] + bb.y, 0.f));
                        atomicAdd((float2*)(agg + (size_t)rv1 * 128 + col), v1);
                    }
                }
            }
        }
    }
}

// =====================================================================================
// node_update: upd = LN(concat(nh, agg) @ Wu + b); out = n + upd. K=256, N=128.
// =====================================================================================
__global__ __launch_bounds__(512, 1)
void node_update_f16(const float* __restrict__ nf, const __half* __restrict__ nh,
                     const float* __restrict__ agg, const __half* __restrict__ Wut,
                     const float* __restrict__ bias,
                     const float* __restrict__ lns, const float* __restrict__ lno,
                     float* __restrict__ outf, __half* __restrict__ outh, int M)
{
    extern __shared__ char sm[];
    char* Asm = sm;
    char* Bsm = sm + 67584;
    const int tid = threadIdx.x, w = tid >> 5, lane = tid & 31;
    const size_t row0 = (size_t)blockIdx.x * 128;

    for (int i = tid; i < 128 * 32; i += 512) {
        int r = i >> 5, c = i & 31, k0 = c * 8;
        uint32_t o[4] = {0, 0, 0, 0};
        size_t row = row0 + r;
        if (row < (size_t)M) {
            if (k0 < 128) {
                *(uint4*)o = *(const uint4*)(nh + row * 128 + k0);
            } else {
                const float* src = agg + row * 128 + (k0 - 128);
                float4 a = ((const float4*)src)[0], b = ((const float4*)src)[1];
                __half2 h0 = __floats2half2_rn(a.x, a.y), h1 = __floats2half2_rn(a.z, a.w);
                __half2 h2 = __floats2half2_rn(b.x, b.y), h3 = __floats2half2_rn(b.z, b.w);
                o[0] = *(uint32_t*)&h0; o[1] = *(uint32_t*)&h1; o[2] = *(uint32_t*)&h2; o[3] = *(uint32_t*)&h3;
            }
        }
        *(uint4*)(Asm + r * 528 + c * 16) = *(uint4*)o;
    }
    stage_w<256>(Bsm, Wut, 128);
    __syncthreads();

    float acc[2][4][4] = {};
    mma_loop<256, 4>(s2u(Asm), s2u(Bsm), acc, w >> 2, w & 3, lane);
    __syncthreads();

    float* Csm = (float*)Asm;
    const int gid = lane >> 2, tig = lane & 3;
    const int rb = (w >> 2) * 32 + gid, cb = (w & 3) * 32 + tig * 2;
#pragma unroll
    for (int i = 0; i < 2; i++)
#pragma unroll
        for (int nt = 0; nt < 4; nt++) {
            int col = cb + nt * 8;
            int r = rb + i * 16;
            Csm[r * 132 + col]           = acc[i][nt][0] + bias[col];
            Csm[r * 132 + col + 1]       = acc[i][nt][1] + bias[col + 1];
            Csm[(r + 8) * 132 + col]     = acc[i][nt][2] + bias[col];
            Csm[(r + 8) * 132 + col + 1] = acc[i][nt][3] + bias[col + 1];
        }
    __syncthreads();

    int r = tid >> 2, s = tid & 3;
    float4 v[8];
    float sum = 0.f;
#pragma unroll
    for (int k = 0; k < 8; k++) {
        v[k] = *(float4*)&Csm[r * 132 + s * 4 + k * 16];
        sum += v[k].x + v[k].y + v[k].z + v[k].w;
    }
    sum += __shfl_xor_sync(0xffffffffu, sum, 1);
    sum += __shfl_xor_sync(0xffffffffu, sum, 2);
    float mean = sum * (1.0f / 128.0f);
    float q = 0.f;
#pragma unroll
    for (int k = 0; k < 8; k++) {
        float dx = v[k].x - mean, dy = v[k].y - mean, dz = v[k].z - mean, dw = v[k].w - mean;
        q += dx * dx + dy * dy + dz * dz + dw * dw;
    }
    q += __shfl_xor_sync(0xffffffffu, q, 1);
    q += __shfl_xor_sync(0xffffffffu, q, 2);
    float rstd = rsqrtf(q * (1.0f / 128.0f) + 1e-5f);

    size_t row = row0 + r;
    if (row < (size_t)M) {
#pragma unroll
        for (int k = 0; k < 8; k++) {
            int col = s * 4 + k * 16;
            float4 sc = *(const float4*)(lns + col), of = *(const float4*)(lno + col);
            float4 res = *(const float4*)(nf + row * 128 + col);
            float4 o;
            o.x = res.x + (v[k].x - mean) * rstd * sc.x + of.x;
            o.y = res.y + (v[k].y - mean) * rstd * sc.y + of.y;
            o.z = res.z + (v[k].z - mean) * rstd * sc.z + of.z;
            o.w = res.w + (v[k].w - mean) * rstd * sc.w + of.w;
            if (outf) *(float4*)(outf + row * 128 + col) = o;
            if (outh) {
                __half2 h0 = __floats2half2_rn(o.x, o.y), h1 = __floats2half2_rn(o.z, o.w);
                ((uint32_t*)(outh + row * 128 + col))[0] = *(uint32_t*)&h0;
                ((uint32_t*)(outh + row * 128 + col))[1] = *(uint32_t*)&h1;
            }
        }
    }
}

// =====================================================================================
extern "C" void kernel_launch(void* const* d_in, const int* in_sizes, int n_in,
                              void* d_out, int out_size)
{
    const float* nodes     = (const float*)d_in[0];
    const float* edges     = (const float*)d_in[1];
    const int*   senders   = (const int*)d_in[2];
    const int*   receivers = (const int*)d_in[3];
    const float* w_node    = (const float*)d_in[4];
    const float* b_node    = (const float*)d_in[5];
    const float* w_edge    = (const float*)d_in[6];
    const float* b_edge    = (const float*)d_in[7];
    const float* ln_n_s    = (const float*)d_in[8];
    const float* ln_n_o    = (const float*)d_in[9];
    const float* ln_e_s    = (const float*)d_in[10];
    const float* ln_e_o    = (const float*)d_in[11];
    const float* msg_w1    = (const float*)d_in[12];
    const float* msg_b1    = (const float*)d_in[13];
    const float* msg_w2    = (const float*)d_in[14];
    const float* msg_b2    = (const float*)d_in[15];
    const float* upd_w     = (const float*)d_in[16];
    const float* upd_b     = (const float*)d_in[17];
    const float* ln_s      = (const float*)d_in[18];
    const float* ln_o      = (const float*)d_in[19];

    const int N = in_sizes[0] / D;
    const int E = in_sizes[1] / D;

    int dev = 0, nsm = 148;
    cudaGetDevice(&dev);
    cudaDeviceGetAttribute(&nsm, cudaDevAttrMultiProcessorCount, dev);

    float *pn, *pagg;
    __half *pnh, *peh, *pPs, *pPr, *pwnt, *pwet, *pw1t, *pw2t, *pwut;
    cudaGetSymbolAddress((void**)&pn,   g_n);
    cudaGetSymbolAddress((void**)&pagg, g_agg);
    cudaGetSymbolAddress((void**)&pnh,  g_nh);
    cudaGetSymbolAddress((void**)&peh,  g_eh);
    cudaGetSymbolAddress((void**)&pPs,  g_Psh);
    cudaGetSymbolAddress((void**)&pPr,  g_Prh);
    cudaGetSymbolAddress((void**)&pwnt, g_wnt);
    cudaGetSymbolAddress((void**)&pwet, g_wet);
    cudaGetSymbolAddress((void**)&pw1t, g_w1t);
    cudaGetSymbolAddress((void**)&pw2t, g_w2t);
    cudaGetSymbolAddress((void**)&pwut, g_wut);

    const size_t embed_smem = 69632;
    const size_t g12_smem   = 174080;
    const size_t ws_smem    = 230912;   // fixed: includes b1h (was 256B short -> IMA)
    const size_t upd_smem   = 135168;

    cudaFuncSetAttribute(embed_f16,       cudaFuncAttributeMaxDynamicSharedMemorySize, (int)embed_smem);
    cudaFuncSetAttribute(gemm1x2_f16,     cudaFuncAttributeMaxDynamicSharedMemorySize, (int)g12_smem);
    cudaFuncSetAttribute(edge_ws_f16,     cudaFuncAttributeMaxDynamicSharedMemorySize, (int)ws_smem);
    cudaFuncSetAttribute(node_update_f16, cudaFuncAttributeMaxDynamicSharedMemorySize, (int)upd_smem);

    // ---- all weight transposes in one launch ----
    transpose_all<<<dim3(8, 8, 17), 256>>>(w_node, w_edge, msg_w1, msg_w2, upd_w,
                                           pwnt, pwet, pw1t, pw2t, pwut);

    // ---- embeddings ----
    embed_f16<<<(N + 127) / 128, 512, embed_smem>>>(nodes, pwnt, b_node, ln_n_s, ln_n_o, pn, pnh, N);
    embed_f16<<<(E + 127) / 128, 512, embed_smem>>>(edges, pwet, b_edge, ln_e_s, ln_e_o, (float*)nullptr, peh, E);

    // ---- layers ----
    for (int l = 0; l < 3; l++) {
        gemm1x2_f16<<<(N + 127) / 128, 512, g12_smem>>>(
            pnh, pw1t + (size_t)(l * 3 + 0) * 32768, pw1t + (size_t)(l * 3 + 1) * 32768,
            pPs, pPr, N);
        cudaMemsetAsync(pagg, 0, (size_t)N * D * sizeof(float), 0);
        edge_ws_f16<<<nsm, 512, ws_smem>>>(
            peh, pPs, pPr,
            pw1t + (size_t)(l * 3 + 2) * 32768, msg_b1 + (size_t)l * 256,
            pw2t + (size_t)l * 32768, msg_b2 + (size_t)l * 128,
            senders, receivers, pagg, E);
        float* nout = (l == 2) ? (float*)d_out : pn;
        __half* nhout = (l == 2) ? (__half*)nullptr : pnh;
        node_update_f16<<<(N + 127) / 128, 512, upd_smem>>>(
            pn, pnh, pagg, pwut + (size_t)l * 32768, upd_b + (size_t)l * 128,
            ln_s + (size_t)l * 128, ln_o + (size_t)l * 128, nout, nhout, N);
    }
}